// round 14
// baseline (speedup 1.0000x reference)
#include <cuda_runtime.h>
#include <cuda_fp16.h>
#include <cstdint>

#define B_ 256
#define I_ 1152
#define N_ 10
#define D_ 16
#define K_ 8

// u_hat scratch, layout [b][n][i][d], fp16 = 94 MB (L2-resident)
__device__ __half g_uhat[(size_t)B_ * N_ * I_ * D_];

// ---------------- helpers ----------------
__device__ __forceinline__ unsigned long long pack2(float a, float b) {
    unsigned long long r;
    asm("mov.b64 %0, {%1, %2};" : "=l"(r) : "f"(a), "f"(b));
    return r;
}
__device__ __forceinline__ unsigned long long fma2(unsigned long long a,
                                                   unsigned long long b,
                                                   unsigned long long c) {
    unsigned long long r;
    asm("fma.rn.f32x2 %0, %1, %2, %3;" : "=l"(r) : "l"(a), "l"(b), "l"(c));
    return r;
}
__device__ __forceinline__ void unpack2(unsigned long long v, float& lo, float& hi) {
    asm("mov.b64 {%0, %1}, %2;" : "=f"(lo), "=f"(hi) : "l"(v));
}
__device__ __forceinline__ unsigned int cvt2h(unsigned long long v) {
    float lo, hi;
    unpack2(v, lo, hi);
    __half2 h = __floats2half2_rn(lo, hi);
    return *reinterpret_cast<unsigned int*>(&h);
}

// ---------------- kernel 1: u_hat = einsum('nidk,bik->bnid') fp16 -------------
__global__ __launch_bounds__(320, 2) void k_uhat(const float* __restrict__ x,
                                                 const float* __restrict__ W) {
    __shared__ unsigned long long sx[256 * 32];  // 64 KB: [bl][iloc*8+k]
    const int tid = threadIdx.x;
    const int i0 = blockIdx.x * 4;

    const int bq   = tid / 80;
    const int t    = tid - bq * 80;
    const int dh   = t & 1;
    const int n    = (t >> 1) % 10;
    const int iloc = t / 20;

    unsigned long long w2[8][4];
    {
        float wv[8][8];
        const float* wp = W + (((size_t)n * I_ + i0 + iloc) * D_ + dh * 8) * K_;
#pragma unroll
        for (int d = 0; d < 8; d++) {
            float4 a = *(const float4*)(wp + d * 8);
            float4 c = *(const float4*)(wp + d * 8 + 4);
            wv[d][0] = a.x; wv[d][1] = a.y; wv[d][2] = a.z; wv[d][3] = a.w;
            wv[d][4] = c.x; wv[d][5] = c.y; wv[d][6] = c.z; wv[d][7] = c.w;
        }
#pragma unroll
        for (int k = 0; k < 8; k++)
#pragma unroll
            for (int p = 0; p < 4; p++)
                w2[k][p] = pack2(wv[2 * p][k], wv[2 * p + 1][k]);
    }

    for (int idx = tid; idx < 8192; idx += 320) {
        int bl = idx >> 5, rem = idx & 31;
        float v = x[(size_t)bl * (I_ * K_) + i0 * K_ + rem];
        sx[idx] = pack2(v, v);
    }
    __syncthreads();

    const int b0 = bq * 64;
#pragma unroll 2
    for (int j = 0; j < 64; j++) {
        const int bl = b0 + j;
        const ulonglong2* xr = (const ulonglong2*)(sx + bl * 32 + iloc * 8);
        unsigned long long a0 = 0ull, a1 = 0ull, a2 = 0ull, a3 = 0ull;
#pragma unroll
        for (int kp = 0; kp < 4; kp++) {
            ulonglong2 xx = xr[kp];
            a0 = fma2(w2[2 * kp][0], xx.x, a0);
            a1 = fma2(w2[2 * kp][1], xx.x, a1);
            a2 = fma2(w2[2 * kp][2], xx.x, a2);
            a3 = fma2(w2[2 * kp][3], xx.x, a3);
            a0 = fma2(w2[2 * kp + 1][0], xx.y, a0);
            a1 = fma2(w2[2 * kp + 1][1], xx.y, a1);
            a2 = fma2(w2[2 * kp + 1][2], xx.y, a2);
            a3 = fma2(w2[2 * kp + 1][3], xx.y, a3);
        }
        uint4 r;
        r.x = cvt2h(a0); r.y = cvt2h(a1); r.z = cvt2h(a2); r.w = cvt2h(a3);
        *(uint4*)(g_uhat + (((size_t)bl * N_ + n) * I_ + i0 + iloc) * D_ + dh * 8) = r;
    }
}

// ---------------- kernel 2: routing, fused softmax+accumulate, 1 u-pass/iter --
// 384 threads. Lane quad: ng = lane&3 owns n-group {0-2 | 3-5 | 6-7 | 8-9};
// ihh = lane>>2 spans 8 i. Warp covers 8 i/round, 12 warps -> 96 i/round,
// 12 rounds = 1152 i. Phase A computes this thread's logits (fp16 dots vs
// ocum_h), quad exchanges exp-sums, phase B re-reads u (L1 hit) and
// accumulates c*u into 48 f32 regs.
#define RTH 384

__global__ __launch_bounds__(RTH, 2) void k_route(float* __restrict__ out) {
    __shared__ __align__(16) float sPart[12 * 164];
    __shared__ __align__(16) float stot[160];
    __shared__ __align__(16) float ocum[160];
    __shared__ __align__(16) unsigned int ocum_h[80];   // ocum*log2e as half2

    const int tid = threadIdx.x;
    const int b = blockIdx.x;
    const __half* ub = g_uhat + (size_t)b * N_ * I_ * D_;

    const int w = tid >> 5, lane = tid & 31;
    const int ihh = lane >> 2, ng = lane & 3;
    const int nstart = (ng < 2) ? ng * 3 : 6 + (ng - 2) * 2;   // 0,3,6,8
    const int ncnt   = (ng < 2) ? 3 : 2;

#pragma unroll 1
    for (int r = 0; r < 3; r++) {
        unsigned long long acc[3][8];
#pragma unroll
        for (int j = 0; j < 3; j++)
#pragma unroll
            for (int q = 0; q < 8; q++) acc[j][q] = 0ull;

#pragma unroll 1
        for (int round = 0; round < 12; round++) {
            const int i = round * 96 + w * 8 + ihh;
            const __half* ibase = ub + (size_t)i * D_;

            float c[3];
            if (r == 0) {
                c[0] = c[1] = c[2] = 0.1f;
            } else {
                // ---- phase A: logits for own n-group (fp16 dots) ----
                float ex[3];
                float partial = 0.0f;
#pragma unroll
                for (int j = 0; j < 3; j++) {
                    if (j < ncnt) {
                        const int n = nstart + j;
                        const uint4* p = (const uint4*)(ibase + (size_t)n * (I_ * D_));
                        uint4 v0 = p[0], v1 = p[1];
                        uint4 o0 = ((const uint4*)ocum_h)[n * 2];
                        uint4 o1 = ((const uint4*)ocum_h)[n * 2 + 1];
                        __half2 a2 = __float2half2_rn(0.0f);
                        a2 = __hfma2(*(const __half2*)&v0.x, *(const __half2*)&o0.x, a2);
                        a2 = __hfma2(*(const __half2*)&v0.y, *(const __half2*)&o0.y, a2);
                        a2 = __hfma2(*(const __half2*)&v0.z, *(const __half2*)&o0.z, a2);
                        a2 = __hfma2(*(const __half2*)&v0.w, *(const __half2*)&o0.w, a2);
                        a2 = __hfma2(*(const __half2*)&v1.x, *(const __half2*)&o1.x, a2);
                        a2 = __hfma2(*(const __half2*)&v1.y, *(const __half2*)&o1.y, a2);
                        a2 = __hfma2(*(const __half2*)&v1.z, *(const __half2*)&o1.z, a2);
                        a2 = __hfma2(*(const __half2*)&v1.w, *(const __half2*)&o1.w, a2);
                        float2 fa = __half22float2(a2);
                        ex[j] = exp2f(fa.x + fa.y);   // pre-scaled by log2e
                        partial += ex[j];
                    }
                }
                // quad exchange of exp-sums (full softmax denominator)
                partial += __shfl_xor_sync(0xffffffffu, partial, 1);
                partial += __shfl_xor_sync(0xffffffffu, partial, 2);
                float inv = __fdividef(1.0f, partial);
#pragma unroll
                for (int j = 0; j < 3; j++) c[j] = ex[j] * inv;
            }

            // ---- phase B: re-read u (L1 hit) and accumulate c*u ----
#pragma unroll
            for (int j = 0; j < 3; j++) {
                if (j < ncnt) {
                    const __half* gp = ibase + (size_t)(nstart + j) * (I_ * D_);
                    uint4 v0, v1;
                    asm volatile("ld.global.nc.v4.u32 {%0,%1,%2,%3}, [%4];"
                                 : "=r"(v0.x), "=r"(v0.y), "=r"(v0.z), "=r"(v0.w)
                                 : "l"(gp));
                    asm volatile("ld.global.nc.v4.u32 {%0,%1,%2,%3}, [%4];"
                                 : "=r"(v1.x), "=r"(v1.y), "=r"(v1.z), "=r"(v1.w)
                                 : "l"(gp + 8));
                    unsigned long long cc = pack2(c[j], c[j]);
                    float2 f;
                    f = __half22float2(*(const __half2*)&v0.x);
                    acc[j][0] = fma2(pack2(f.x, f.y), cc, acc[j][0]);
                    f = __half22float2(*(const __half2*)&v0.y);
                    acc[j][1] = fma2(pack2(f.x, f.y), cc, acc[j][1]);
                    f = __half22float2(*(const __half2*)&v0.z);
                    acc[j][2] = fma2(pack2(f.x, f.y), cc, acc[j][2]);
                    f = __half22float2(*(const __half2*)&v0.w);
                    acc[j][3] = fma2(pack2(f.x, f.y), cc, acc[j][3]);
                    f = __half22float2(*(const __half2*)&v1.x);
                    acc[j][4] = fma2(pack2(f.x, f.y), cc, acc[j][4]);
                    f = __half22float2(*(const __half2*)&v1.y);
                    acc[j][5] = fma2(pack2(f.x, f.y), cc, acc[j][5]);
                    f = __half22float2(*(const __half2*)&v1.z);
                    acc[j][6] = fma2(pack2(f.x, f.y), cc, acc[j][6]);
                    f = __half22float2(*(const __half2*)&v1.w);
                    acc[j][7] = fma2(pack2(f.x, f.y), cc, acc[j][7]);
                }
            }
        }

        // ---- unpack acc, reduce over the 8 ihh lanes ----
        float s[3][16];
#pragma unroll
        for (int j = 0; j < 3; j++)
#pragma unroll
            for (int q = 0; q < 8; q++)
                unpack2(acc[j][q], s[j][2 * q], s[j][2 * q + 1]);

#pragma unroll
        for (int ofs = 4; ofs <= 16; ofs <<= 1)
#pragma unroll
            for (int j = 0; j < 3; j++)
#pragma unroll
                for (int d = 0; d < 16; d++)
                    s[j][d] += __shfl_xor_sync(0xffffffffu, s[j][d], ofs);

        if (ihh == 0) {
#pragma unroll
            for (int j = 0; j < 3; j++) {
                if (j < ncnt) {
                    const int n = nstart + j;
#pragma unroll
                    for (int q = 0; q < 4; q++)
                        *(float4*)&sPart[w * 164 + n * 16 + q * 4] =
                            make_float4(s[j][4 * q], s[j][4 * q + 1],
                                        s[j][4 * q + 2], s[j][4 * q + 3]);
                }
            }
        }
        __syncthreads();

        if (tid < 160) {
            float sum = 0.0f;
#pragma unroll
            for (int ww = 0; ww < 12; ww++) sum += sPart[ww * 164 + tid];
            stot[tid] = sum;
        }
        __syncthreads();

        if (tid < 160) {
            const int n = tid >> 4;
            float ns = 0.0f;
#pragma unroll
            for (int d = 0; d < 16; d++) {
                float tv = stot[n * 16 + d];
                ns += tv * tv;
            }
            float f = sqrtf(ns) / (1.0f + ns);
            float val = stot[tid] * f;
            if (r < 2) ocum[tid] = (r == 0) ? val : ocum[tid] + val;
            else       out[b * 160 + tid] = val;
        }
        __syncthreads();

        if (r < 2) {
            if (tid < 80) {
                const float L2E = 1.44269504f;
                __half2 h = __floats2half2_rn(ocum[tid * 2] * L2E,
                                              ocum[tid * 2 + 1] * L2E);
                ocum_h[tid] = *reinterpret_cast<unsigned int*>(&h);
            }
            __syncthreads();
        }
    }
}

// ---------------- launch ----------------
extern "C" void kernel_launch(void* const* d_in, const int* in_sizes, int n_in,
                              void* d_out, int out_size) {
    const float* x = (const float*)d_in[0];   // inputs [B, I, Din]
    const float* W = (const float*)d_in[1];   // W      [N, I, D, Din]
    if (n_in >= 2 && in_sizes[0] == N_ * I_ * D_ * K_) {
        const float* t = x; x = W; W = t;
    }
    float* out = (float*)d_out;

    k_uhat<<<I_ / 4, 320>>>(x, W);
    k_route<<<B_, RTH>>>(out);
}

// round 15
// speedup vs baseline: 1.5019x; 1.5019x over previous
#include <cuda_runtime.h>
#include <cuda_fp16.h>
#include <cstdint>

#define B_ 256
#define I_ 1152
#define N_ 10
#define D_ 16
#define K_ 8

// u_hat scratch, layout [b][n][i][d], fp16 = 94 MB (L2-resident)
__device__ __half g_uhat[(size_t)B_ * N_ * I_ * D_];

// ---------------- helpers ----------------
__device__ __forceinline__ unsigned long long pack2(float a, float b) {
    unsigned long long r;
    asm("mov.b64 %0, {%1, %2};" : "=l"(r) : "f"(a), "f"(b));
    return r;
}
__device__ __forceinline__ unsigned long long fma2(unsigned long long a,
                                                   unsigned long long b,
                                                   unsigned long long c) {
    unsigned long long r;
    asm("fma.rn.f32x2 %0, %1, %2, %3;" : "=l"(r) : "l"(a), "l"(b), "l"(c));
    return r;
}
__device__ __forceinline__ void unpack2(unsigned long long v, float& lo, float& hi) {
    asm("mov.b64 {%0, %1}, %2;" : "=f"(lo), "=f"(hi) : "l"(v));
}
__device__ __forceinline__ unsigned int cvt2h(unsigned long long v) {
    float lo, hi;
    unpack2(v, lo, hi);
    __half2 h = __floats2half2_rn(lo, hi);
    return *reinterpret_cast<unsigned int*>(&h);
}

// ---------------- kernel 1: u_hat = einsum('nidk,bik->bnid') fp16 -------------
__global__ __launch_bounds__(320, 2) void k_uhat(const float* __restrict__ x,
                                                 const float* __restrict__ W) {
    __shared__ unsigned long long sx[256 * 32];  // 64 KB: [bl][iloc*8+k]
    const int tid = threadIdx.x;
    const int i0 = blockIdx.x * 4;

    const int bq   = tid / 80;
    const int t    = tid - bq * 80;
    const int dh   = t & 1;
    const int n    = (t >> 1) % 10;
    const int iloc = t / 20;

    unsigned long long w2[8][4];
    {
        float wv[8][8];
        const float* wp = W + (((size_t)n * I_ + i0 + iloc) * D_ + dh * 8) * K_;
#pragma unroll
        for (int d = 0; d < 8; d++) {
            float4 a = *(const float4*)(wp + d * 8);
            float4 c = *(const float4*)(wp + d * 8 + 4);
            wv[d][0] = a.x; wv[d][1] = a.y; wv[d][2] = a.z; wv[d][3] = a.w;
            wv[d][4] = c.x; wv[d][5] = c.y; wv[d][6] = c.z; wv[d][7] = c.w;
        }
#pragma unroll
        for (int k = 0; k < 8; k++)
#pragma unroll
            for (int p = 0; p < 4; p++)
                w2[k][p] = pack2(wv[2 * p][k], wv[2 * p + 1][k]);
    }

    for (int idx = tid; idx < 8192; idx += 320) {
        int bl = idx >> 5, rem = idx & 31;
        float v = x[(size_t)bl * (I_ * K_) + i0 * K_ + rem];
        sx[idx] = pack2(v, v);
    }
    __syncthreads();

    const int b0 = bq * 64;
#pragma unroll 2
    for (int j = 0; j < 64; j++) {
        const int bl = b0 + j;
        const ulonglong2* xr = (const ulonglong2*)(sx + bl * 32 + iloc * 8);
        unsigned long long a0 = 0ull, a1 = 0ull, a2 = 0ull, a3 = 0ull;
#pragma unroll
        for (int kp = 0; kp < 4; kp++) {
            ulonglong2 xx = xr[kp];
            a0 = fma2(w2[2 * kp][0], xx.x, a0);
            a1 = fma2(w2[2 * kp][1], xx.x, a1);
            a2 = fma2(w2[2 * kp][2], xx.x, a2);
            a3 = fma2(w2[2 * kp][3], xx.x, a3);
            a0 = fma2(w2[2 * kp + 1][0], xx.y, a0);
            a1 = fma2(w2[2 * kp + 1][1], xx.y, a1);
            a2 = fma2(w2[2 * kp + 1][2], xx.y, a2);
            a3 = fma2(w2[2 * kp + 1][3], xx.y, a3);
        }
        uint4 r;
        r.x = cvt2h(a0); r.y = cvt2h(a1); r.z = cvt2h(a2); r.w = cvt2h(a3);
        *(uint4*)(g_uhat + (((size_t)bl * N_ + n) * I_ + i0 + iloc) * D_ + dh * 8) = r;
    }
}

// ---------------- kernel 2: routing, 576 threads per b ------------------------
#define RTH 576
#define CSTRIDE 1160

__device__ __forceinline__ void sweepB(const __half* __restrict__ ub,
                                       const float* __restrict__ cbuf,
                                       unsigned long long sp[5][2],
                                       int nbase, int wg, int il, int dq,
                                       bool constC) {
    const int ioff = wg * 8 + il;
    const __half* ubase0 = ub + ((size_t)nbase * I_) * D_ + dq * 4;

    uint2 v[5];
#pragma unroll
    for (int n = 0; n < 5; n++)
        v[n] = *(const uint2*)(ubase0 + ((size_t)n * I_ + ioff) * D_);

#pragma unroll 1
    for (int round = 0; round < 16; round++) {
        const int i = round * 72 + ioff;
        // prefetch next round (clamped so last round re-reads its own lines)
        const int inext = (round < 15 ? (round + 1) * 72 : round * 72) + ioff;
        uint2 vn[5];
#pragma unroll
        for (int n = 0; n < 5; n++)
            vn[n] = *(const uint2*)(ubase0 + ((size_t)n * I_ + inext) * D_);

#pragma unroll
        for (int n = 0; n < 5; n++) {
            float2 f0 = __half22float2(*(const __half2*)&v[n].x);
            float2 f1 = __half22float2(*(const __half2*)&v[n].y);
            float cv = constC ? 0.1f : cbuf[(nbase + n) * CSTRIDE + i];
            unsigned long long cc = pack2(cv, cv);
            sp[n][0] = fma2(pack2(f0.x, f0.y), cc, sp[n][0]);
            sp[n][1] = fma2(pack2(f1.x, f1.y), cc, sp[n][1]);
        }
#pragma unroll
        for (int n = 0; n < 5; n++) v[n] = vn[n];
    }
}

__global__ __launch_bounds__(RTH, 2) void k_route(float* __restrict__ out) {
    __shared__ __align__(16) float cbuf[10 * CSTRIDE];   // 46.4 KB, whole I
    __shared__ __align__(16) float sPart[18 * 80];
    __shared__ __align__(16) float stot[160];
    __shared__ __align__(16) float ocum[160];
    __shared__ __align__(16) unsigned int ocum_h[80];    // ocum*log2e as half2

    const int tid = threadIdx.x;
    const int b = blockIdx.x;
    const __half* ub = g_uhat + (size_t)b * N_ * I_ * D_;

    const int w = tid >> 5, lane = tid & 31;
    const int il = lane >> 2, dq = lane & 3;
    const int nh = w & 1, wg = w >> 1;
    const int nbase = nh * 5;

#pragma unroll 1
    for (int r = 0; r < 3; r++) {
        // ---- sweep A over ALL I: 256-bit loads, full-d per thread ----
        if (r > 0) {
#pragma unroll 1
            for (int i = tid; i < I_; i += RTH) {
                float lg[10];
#pragma unroll 2
                for (int n = 0; n < 10; n++) {
                    unsigned int u0, u1, u2, u3, u4, u5, u6, u7;
                    asm volatile(
                        "ld.global.v8.b32 {%0,%1,%2,%3,%4,%5,%6,%7}, [%8];"
                        : "=r"(u0), "=r"(u1), "=r"(u2), "=r"(u3),
                          "=r"(u4), "=r"(u5), "=r"(u6), "=r"(u7)
                        : "l"(ub + ((size_t)n * I_ + i) * D_));
                    uint4 o0 = ((const uint4*)ocum_h)[n * 2];
                    uint4 o1 = ((const uint4*)ocum_h)[n * 2 + 1];
                    __half2 a2 = __float2half2_rn(0.0f);
                    a2 = __hfma2(*(const __half2*)&u0, *(const __half2*)&o0.x, a2);
                    a2 = __hfma2(*(const __half2*)&u1, *(const __half2*)&o0.y, a2);
                    a2 = __hfma2(*(const __half2*)&u2, *(const __half2*)&o0.z, a2);
                    a2 = __hfma2(*(const __half2*)&u3, *(const __half2*)&o0.w, a2);
                    a2 = __hfma2(*(const __half2*)&u4, *(const __half2*)&o1.x, a2);
                    a2 = __hfma2(*(const __half2*)&u5, *(const __half2*)&o1.y, a2);
                    a2 = __hfma2(*(const __half2*)&u6, *(const __half2*)&o1.z, a2);
                    a2 = __hfma2(*(const __half2*)&u7, *(const __half2*)&o1.w, a2);
                    float2 fa = __half22float2(a2);
                    lg[n] = fa.x + fa.y;           // pre-scaled by log2e
                }
                float sum = 0.0f;
#pragma unroll
                for (int n = 0; n < 10; n++) { lg[n] = exp2f(lg[n]); sum += lg[n]; }
                float inv = __fdividef(1.0f, sum);
#pragma unroll
                for (int n = 0; n < 10; n++) cbuf[n * CSTRIDE + i] = lg[n] * inv;
            }
            __syncthreads();
        }

        // ---- sweep B (software-pipelined loads) ----
        unsigned long long sp[5][2];
#pragma unroll
        for (int n = 0; n < 5; n++) { sp[n][0] = 0ull; sp[n][1] = 0ull; }

        if (r == 0) sweepB(ub, cbuf, sp, nbase, wg, il, dq, true);
        else        sweepB(ub, cbuf, sp, nbase, wg, il, dq, false);

        float s4[5][4];
#pragma unroll
        for (int n = 0; n < 5; n++) {
            unpack2(sp[n][0], s4[n][0], s4[n][1]);
            unpack2(sp[n][1], s4[n][2], s4[n][3]);
        }
#pragma unroll
        for (int ofs = 4; ofs <= 16; ofs <<= 1)
#pragma unroll
            for (int n = 0; n < 5; n++)
#pragma unroll
                for (int q = 0; q < 4; q++)
                    s4[n][q] += __shfl_xor_sync(0xffffffffu, s4[n][q], ofs);

        if (il == 0) {
#pragma unroll
            for (int n = 0; n < 5; n++)
                *(float4*)&sPart[w * 80 + n * 16 + dq * 4] =
                    make_float4(s4[n][0], s4[n][1], s4[n][2], s4[n][3]);
        }
        __syncthreads();

        if (tid < 160) {
            const int n = tid >> 4;
            const int nh2 = (n >= 5);
            const int col = (n - nh2 * 5) * 16 + (tid & 15);
            float s = 0.0f;
#pragma unroll
            for (int j = 0; j < 9; j++) s += sPart[(j * 2 + nh2) * 80 + col];
            stot[tid] = s;
        }
        __syncthreads();

        if (tid < 160) {
            const int n = tid >> 4;
            float ns = 0.0f;
#pragma unroll
            for (int j = 0; j < 16; j++) {
                float tv = stot[n * 16 + j];
                ns += tv * tv;
            }
            float f = sqrtf(ns) / (1.0f + ns);
            float val = stot[tid] * f;
            if (r < 2) ocum[tid] = (r == 0) ? val : ocum[tid] + val;
            else       out[b * 160 + tid] = val;
        }
        __syncthreads();

        if (r < 2) {
            if (tid < 80) {
                const float L2E = 1.44269504f;
                __half2 h = __floats2half2_rn(ocum[tid * 2] * L2E,
                                              ocum[tid * 2 + 1] * L2E);
                ocum_h[tid] = *reinterpret_cast<unsigned int*>(&h);
            }
            __syncthreads();
        }
    }
}

// ---------------- launch ----------------
extern "C" void kernel_launch(void* const* d_in, const int* in_sizes, int n_in,
                              void* d_out, int out_size) {
    const float* x = (const float*)d_in[0];   // inputs [B, I, Din]
    const float* W = (const float*)d_in[1];   // W      [N, I, D, Din]
    if (n_in >= 2 && in_sizes[0] == N_ * I_ * D_ * K_) {
        const float* t = x; x = W; W = t;
    }
    float* out = (float*)d_out;

    k_uhat<<<I_ / 4, 320>>>(x, W);
    k_route<<<B_, RTH>>>(out);
}

// round 17
// speedup vs baseline: 1.5951x; 1.0621x over previous
#include <cuda_runtime.h>
#include <cuda_fp16.h>
#include <cstdint>

#define B_ 256
#define I_ 1152
#define N_ 10
#define D_ 16
#define K_ 8
#define NSTR (I_ * D_)   // 18432 halves between n-blocks

// u_hat scratch, layout [b][n][i][d], fp16 = 94 MB (L2-resident)
__device__ __half g_uhat[(size_t)B_ * N_ * I_ * D_];

// ---------------- helpers ----------------
__device__ __forceinline__ unsigned long long pack2(float a, float b) {
    unsigned long long r;
    asm("mov.b64 %0, {%1, %2};" : "=l"(r) : "f"(a), "f"(b));
    return r;
}
__device__ __forceinline__ unsigned long long fma2(unsigned long long a,
                                                   unsigned long long b,
                                                   unsigned long long c) {
    unsigned long long r;
    asm("fma.rn.f32x2 %0, %1, %2, %3;" : "=l"(r) : "l"(a), "l"(b), "l"(c));
    return r;
}
__device__ __forceinline__ void unpack2(unsigned long long v, float& lo, float& hi) {
    asm("mov.b64 {%0, %1}, %2;" : "=f"(lo), "=f"(hi) : "l"(v));
}
__device__ __forceinline__ unsigned int cvt2h(unsigned long long v) {
    float lo, hi;
    unpack2(v, lo, hi);
    __half2 h = __floats2half2_rn(lo, hi);
    return *reinterpret_cast<unsigned int*>(&h);
}

// 256-bit load at compile-time immediate byte offset
template <int OFF>
__device__ __forceinline__ void ldg_v8_imm(const __half* p,
                                           uint4& a, uint4& b) {
    asm volatile(
        "ld.global.v8.b32 {%0,%1,%2,%3,%4,%5,%6,%7}, [%8+%9];"
        : "=r"(a.x), "=r"(a.y), "=r"(a.z), "=r"(a.w),
          "=r"(b.x), "=r"(b.y), "=r"(b.z), "=r"(b.w)
        : "l"(p), "n"(OFF));
}

// ---------------- kernel 1: u_hat = einsum('nidk,bik->bnid') fp16 -------------
__global__ __launch_bounds__(320, 2) void k_uhat(const float* __restrict__ x,
                                                 const float* __restrict__ W) {
    __shared__ unsigned long long sx[256 * 32];  // 64 KB: [bl][iloc*8+k]
    const int tid = threadIdx.x;
    const int i0 = blockIdx.x * 4;

    const int bq   = tid / 80;
    const int t    = tid - bq * 80;
    const int dh   = t & 1;
    const int n    = (t >> 1) % 10;
    const int iloc = t / 20;

    unsigned long long w2[8][4];
    {
        float wv[8][8];
        const float* wp = W + (((size_t)n * I_ + i0 + iloc) * D_ + dh * 8) * K_;
#pragma unroll
        for (int d = 0; d < 8; d++) {
            float4 a = *(const float4*)(wp + d * 8);
            float4 c = *(const float4*)(wp + d * 8 + 4);
            wv[d][0] = a.x; wv[d][1] = a.y; wv[d][2] = a.z; wv[d][3] = a.w;
            wv[d][4] = c.x; wv[d][5] = c.y; wv[d][6] = c.z; wv[d][7] = c.w;
        }
#pragma unroll
        for (int k = 0; k < 8; k++)
#pragma unroll
            for (int p = 0; p < 4; p++)
                w2[k][p] = pack2(wv[2 * p][k], wv[2 * p + 1][k]);
    }

    for (int idx = tid; idx < 8192; idx += 320) {
        int bl = idx >> 5, rem = idx & 31;
        float v = x[(size_t)bl * (I_ * K_) + i0 * K_ + rem];
        sx[idx] = pack2(v, v);
    }
    __syncthreads();

    const int b0 = bq * 64;
    const unsigned long long* xp = sx + b0 * 32 + iloc * 8;
    __half* gp = g_uhat + (((size_t)b0 * N_ + n) * I_ + i0 + iloc) * D_ + dh * 8;
    const size_t bstride = (size_t)N_ * I_ * D_;

#pragma unroll 2
    for (int j = 0; j < 64; j++) {
        const ulonglong2* xr = (const ulonglong2*)xp;
        unsigned long long a0 = 0ull, a1 = 0ull, a2 = 0ull, a3 = 0ull;
#pragma unroll
        for (int kp = 0; kp < 4; kp++) {
            ulonglong2 xx = xr[kp];
            a0 = fma2(w2[2 * kp][0], xx.x, a0);
            a1 = fma2(w2[2 * kp][1], xx.x, a1);
            a2 = fma2(w2[2 * kp][2], xx.x, a2);
            a3 = fma2(w2[2 * kp][3], xx.x, a3);
            a0 = fma2(w2[2 * kp + 1][0], xx.y, a0);
            a1 = fma2(w2[2 * kp + 1][1], xx.y, a1);
            a2 = fma2(w2[2 * kp + 1][2], xx.y, a2);
            a3 = fma2(w2[2 * kp + 1][3], xx.y, a3);
        }
        uint4 r;
        r.x = cvt2h(a0); r.y = cvt2h(a1); r.z = cvt2h(a2); r.w = cvt2h(a3);
        *(uint4*)gp = r;
        xp += 32;
        gp += bstride;
    }
}

// ---------------- kernel 2: routing, 576 threads per b ------------------------
#define RTH 576
#define CSTRIDE 1160

__device__ __forceinline__ void accB(const uint2 v[5], const float* cb,
                                     unsigned long long sp[5][2], bool constC) {
#pragma unroll
    for (int n = 0; n < 5; n++) {
        float2 f0 = __half22float2(*(const __half2*)&v[n].x);
        float2 f1 = __half22float2(*(const __half2*)&v[n].y);
        float cv = constC ? 0.1f : cb[n * CSTRIDE];
        unsigned long long cc = pack2(cv, cv);
        sp[n][0] = fma2(pack2(f0.x, f0.y), cc, sp[n][0]);
        sp[n][1] = fma2(pack2(f1.x, f1.y), cc, sp[n][1]);
    }
}

__device__ __forceinline__ void sweepB(const __half* __restrict__ ub,
                                       const float* __restrict__ cbuf,
                                       unsigned long long sp[5][2],
                                       int nbase, int wg, int il, int dq,
                                       bool constC) {
    const int ioff = wg * 8 + il;
    const __half* p = ub + ((size_t)nbase * I_ + ioff) * D_ + dq * 4;
    const float* cb = cbuf + nbase * CSTRIDE + ioff;

    uint2 v[5];
#pragma unroll
    for (int n = 0; n < 5; n++) v[n] = *(const uint2*)(p + n * NSTR);

#pragma unroll 1
    for (int round = 0; round < 15; round++) {
        uint2 vn[5];
#pragma unroll
        for (int n = 0; n < 5; n++)
            vn[n] = *(const uint2*)(p + 72 * D_ + n * NSTR);
        accB(v, cb, sp, constC);
#pragma unroll
        for (int n = 0; n < 5; n++) v[n] = vn[n];
        p += 72 * D_;
        cb += 72;
    }
    accB(v, cb, sp, constC);   // final round, no prefetch
}

// sweep-A body for one i, logits via compile-time-offset v8 loads
template <int NN>
struct LogitsUnroll {
    static __device__ __forceinline__ void run(const __half* p,
                                               const uint4* oh, float* lg) {
        LogitsUnroll<NN - 1>::run(p, oh, lg);
        constexpr int n = NN - 1;
        uint4 a, b;
        ldg_v8_imm<n * NSTR * 2>(p, a, b);
        uint4 o0 = oh[n * 2];
        uint4 o1 = oh[n * 2 + 1];
        __half2 a2 = __float2half2_rn(0.0f);
        a2 = __hfma2(*(const __half2*)&a.x, *(const __half2*)&o0.x, a2);
        a2 = __hfma2(*(const __half2*)&a.y, *(const __half2*)&o0.y, a2);
        a2 = __hfma2(*(const __half2*)&a.z, *(const __half2*)&o0.z, a2);
        a2 = __hfma2(*(const __half2*)&a.w, *(const __half2*)&o0.w, a2);
        a2 = __hfma2(*(const __half2*)&b.x, *(const __half2*)&o1.x, a2);
        a2 = __hfma2(*(const __half2*)&b.y, *(const __half2*)&o1.y, a2);
        a2 = __hfma2(*(const __half2*)&b.z, *(const __half2*)&o1.z, a2);
        a2 = __hfma2(*(const __half2*)&b.w, *(const __half2*)&o1.w, a2);
        float2 fa = __half22float2(a2);
        lg[n] = fa.x + fa.y;
    }
};
template <>
struct LogitsUnroll<0> {
    static __device__ __forceinline__ void run(const __half*, const uint4*, float*) {}
};

__global__ __launch_bounds__(RTH, 2) void k_route(float* __restrict__ out) {
    __shared__ __align__(16) float cbuf[10 * CSTRIDE];   // 46.4 KB, whole I
    __shared__ __align__(16) float sPart[18 * 80];
    __shared__ __align__(16) float stot[160];
    __shared__ __align__(16) float ocum[160];
    __shared__ __align__(16) unsigned int ocum_h[80];    // ocum*log2e as half2

    const int tid = threadIdx.x;
    const int b = blockIdx.x;
    const __half* ub = g_uhat + (size_t)b * N_ * I_ * D_;

    const int w = tid >> 5, lane = tid & 31;
    const int il = lane >> 2, dq = lane & 3;
    const int nh = w & 1, wg = w >> 1;
    const int nbase = nh * 5;

#pragma unroll 1
    for (int r = 0; r < 3; r++) {
        // ---- sweep A: 2 i's per thread, 256-bit loads, imm offsets ----
        if (r > 0) {
#pragma unroll 1
            for (int it = 0; it < 2; it++) {
                const int i = tid + it * RTH;
                const __half* p = ub + (size_t)i * D_;
                float lg[10];
                LogitsUnroll<10>::run(p, (const uint4*)ocum_h, lg);
                float sum = 0.0f;
#pragma unroll
                for (int n = 0; n < 10; n++) { lg[n] = exp2f(lg[n]); sum += lg[n]; }
                float inv = __fdividef(1.0f, sum);
                float* cw = cbuf + i;
#pragma unroll
                for (int n = 0; n < 10; n++) cw[n * CSTRIDE] = lg[n] * inv;
            }
            __syncthreads();
        }

        // ---- sweep B (pipelined, pointer+imm addressing) ----
        unsigned long long sp[5][2];
#pragma unroll
        for (int n = 0; n < 5; n++) { sp[n][0] = 0ull; sp[n][1] = 0ull; }

        if (r == 0) sweepB(ub, cbuf, sp, nbase, wg, il, dq, true);
        else        sweepB(ub, cbuf, sp, nbase, wg, il, dq, false);

        float s4[5][4];
#pragma unroll
        for (int n = 0; n < 5; n++) {
            unpack2(sp[n][0], s4[n][0], s4[n][1]);
            unpack2(sp[n][1], s4[n][2], s4[n][3]);
        }
#pragma unroll
        for (int ofs = 4; ofs <= 16; ofs <<= 1)
#pragma unroll
            for (int n = 0; n < 5; n++)
#pragma unroll
                for (int q = 0; q < 4; q++)
                    s4[n][q] += __shfl_xor_sync(0xffffffffu, s4[n][q], ofs);

        if (il == 0) {
#pragma unroll
            for (int n = 0; n < 5; n++)
                *(float4*)&sPart[w * 80 + n * 16 + dq * 4] =
                    make_float4(s4[n][0], s4[n][1], s4[n][2], s4[n][3]);
        }
        __syncthreads();

        if (tid < 160) {
            const int n = tid >> 4;
            const int nh2 = (n >= 5);
            const int col = (n - nh2 * 5) * 16 + (tid & 15);
            float s = 0.0f;
#pragma unroll
            for (int j = 0; j < 9; j++) s += sPart[(j * 2 + nh2) * 80 + col];
            stot[tid] = s;
        }
        __syncthreads();

        if (tid < 160) {
            const int n = tid >> 4;
            float ns = 0.0f;
#pragma unroll
            for (int j = 0; j < 16; j++) {
                float tv = stot[n * 16 + j];
                ns += tv * tv;
            }
            float f = sqrtf(ns) / (1.0f + ns);
            float val = stot[tid] * f;
            if (r < 2) ocum[tid] = (r == 0) ? val : ocum[tid] + val;
            else       out[b * 160 + tid] = val;
        }
        __syncthreads();

        if (r < 2) {
            if (tid < 80) {
                const float L2E = 1.44269504f;
                __half2 h = __floats2half2_rn(ocum[tid * 2] * L2E,
                                              ocum[tid * 2 + 1] * L2E);
                ocum_h[tid] = *reinterpret_cast<unsigned int*>(&h);
            }
            __syncthreads();
        }
    }
}

// ---------------- launch ----------------
extern "C" void kernel_launch(void* const* d_in, const int* in_sizes, int n_in,
                              void* d_out, int out_size) {
    const float* x = (const float*)d_in[0];   // inputs [B, I, Din]
    const float* W = (const float*)d_in[1];   // W      [N, I, D, Din]
    if (n_in >= 2 && in_sizes[0] == N_ * I_ * D_ * K_) {
        const float* t = x; x = W; W = t;
    }
    float* out = (float*)d_out;

    k_uhat<<<I_ / 4, 320>>>(x, W);
    k_route<<<B_, RTH>>>(out);
}